// round 6
// baseline (speedup 1.0000x reference)
#include <cuda_runtime.h>
#include <cuda_bf16.h>

#define NBINS 256
#define NCH 3
#define NHIST (NBINS * NCH)     // 768
#define NCOL 16                 // sub-warp columns: lane & 15 -> private-ish column
#define BLOCK_THREADS 256
#define GRID_BLOCKS (148 * 4)   // 592 blocks, 4 CTAs/SM (48 KB smem each)
// GRID_BLOCKS * BLOCK_THREADS = 151552, and 151552 % 3 == 1  -> channel ++ per iter

// Zero at module load; the fused last-block finalize re-zeroes after reading,
// so every call (correctness run and each graph replay) starts from zero.
__device__ unsigned int g_counts[NHIST];
__device__ unsigned int g_ticket;

__device__ __forceinline__ int bin_of(float x) {
    // TF histogram_fixed_width rule: clip(int(x*256), 0, 255), trunc toward zero
    int b = __float2int_rz(x * 256.0f);
    return max(0, min(255, b));
}

__global__ void __launch_bounds__(BLOCK_THREADS, 4)
hist_kernel(const float4* __restrict__ in4, int n4,
            const float* __restrict__ in, int n_total,
            float* __restrict__ out, float inv_total) {
    // Bank-privatized layout: counter (c, bin, col) at sh[(c*256+bin)*16 + col].
    // Bank = 16*(bin&1) + col  ->  only lanes l and l+16 can collide, max degree 2.
    __shared__ unsigned int sh[NHIST * NCOL];   // 49152 B = 48 KB

    for (int i = threadIdx.x; i < NHIST * NCOL; i += BLOCK_THREADS)
        sh[i] = 0u;
    __syncthreads();

    unsigned int* h = sh + (threadIdx.x & (NCOL - 1));   // this lane's column

    const int stride = GRID_BLOCKS * BLOCK_THREADS;
    int j0 = blockIdx.x * BLOCK_THREADS + threadIdx.x;
    int c0 = j0 % 3;   // base channel of float4 j (4 == 1 mod 3)
    for (int j = j0; j < n4; j += stride) {
        float4 v = in4[j];
        int c1 = c0 + 1; if (c1 == 3) c1 = 0;
        int c2 = c1 + 1; if (c2 == 3) c2 = 0;
        atomicAdd(&h[(c0 * NBINS + bin_of(v.x)) * NCOL], 1u);
        atomicAdd(&h[(c1 * NBINS + bin_of(v.y)) * NCOL], 1u);
        atomicAdd(&h[(c2 * NBINS + bin_of(v.z)) * NCOL], 1u);
        atomicAdd(&h[(c0 * NBINS + bin_of(v.w)) * NCOL], 1u);  // 4th wraps to c0
        c0++; if (c0 == 3) c0 = 0;   // stride % 3 == 1
    }

    // Scalar tail (n_total % 4 != 0) — block 0 only (no-op for this shape)
    if (blockIdx.x == 0) {
        for (int i = n4 * 4 + threadIdx.x; i < n_total; i += BLOCK_THREADS) {
            int c = i % 3;
            atomicAdd(&h[(c * NBINS + bin_of(in[i])) * NCOL], 1u);
        }
    }

    __syncthreads();

    // Reduce the 16 columns per bin, publish block partial to L2 counters
    for (int i = threadIdx.x; i < NHIST; i += BLOCK_THREADS) {
        unsigned int s = 0u;
        #pragma unroll
        for (int c = 0; c < NCOL; c++) s += sh[i * NCOL + c];
        if (s) atomicAdd(&g_counts[i], s);
    }

    // Fused finalize: last block to arrive normalizes and resets state.
    __threadfence();
    __shared__ unsigned int ticket;
    if (threadIdx.x == 0) ticket = atomicAdd(&g_ticket, 1u);
    __syncthreads();
    if (ticket == GRID_BLOCKS - 1) {
        for (int i = threadIdx.x; i < NHIST; i += BLOCK_THREADS) {
            unsigned int s = atomicAdd(&g_counts[i], 0u);   // coherent read
            g_counts[i] = 0u;                               // reset for next call
            int c   = i >> 8;
            int bin = i & (NBINS - 1);
            // reference output is hist.T -> [nbins, 3] row-major
            out[bin * NCH + c] = (float)s * inv_total;
        }
        if (threadIdx.x == 0) g_ticket = 0u;                // reset ticket
    }
}

extern "C" void kernel_launch(void* const* d_in, const int* in_sizes, int n_in,
                              void* d_out, int out_size) {
    const float* in = (const float*)d_in[0];
    int n = in_sizes[0];                 // 64*512*512*3 = 50,331,648
    int n4 = n / 4;
    float inv_total = 1.0f / (float)(n / 3);   // per-channel pixel count (exact)

    hist_kernel<<<GRID_BLOCKS, BLOCK_THREADS>>>((const float4*)in, n4, in, n,
                                                (float*)d_out, inv_total);
}

// round 7
// speedup vs baseline: 1.0149x; 1.0149x over previous
#include <cuda_runtime.h>
#include <cuda_bf16.h>

#define NBINS 256
#define NCH 3
#define NHIST (NBINS * NCH)     // 768
#define NCOL 16                 // sub-warp columns: lane & 15 -> private-ish column
#define BLOCK_THREADS 512
#define GRID_BLOCKS (148 * 4)   // 592 blocks = one full wave at 4 CTAs/SM
// stride = GRID_BLOCKS*BLOCK_THREADS = 303104 ; 303104 % 3 == 2

// Zero at module load; the fused last-block finalize re-zeroes after reading,
// so every call (correctness run and each graph replay) starts from zero.
__device__ unsigned int g_counts[NHIST];
__device__ unsigned int g_ticket;

__device__ __forceinline__ int bin_of(float x) {
    // TF histogram_fixed_width rule: clip(int(x*256), 0, 255), trunc toward zero
    int b = __float2int_rz(x * 256.0f);
    return max(0, min(255, b));
}

__global__ void __launch_bounds__(BLOCK_THREADS, 4)
hist_kernel(const float4* __restrict__ in4, int n4,
            const float* __restrict__ in, int n_total,
            float* __restrict__ out, float inv_total) {
    // Bank-privatized layout: counter (c, bin, col) at sh[(c*256+bin)*16 + col].
    // Bank = 16*(bin&1) + col  ->  only lanes l and l+16 can collide, max degree 2.
    __shared__ unsigned int sh[NHIST * NCOL];   // 48 KB -> 4 CTAs/SM, 64 warps/SM

    for (int i = threadIdx.x; i < NHIST * NCOL; i += BLOCK_THREADS)
        sh[i] = 0u;
    __syncthreads();

    unsigned int* h = sh + (threadIdx.x & (NCOL - 1));   // this lane's column

    const int stride = GRID_BLOCKS * BLOCK_THREADS;      // % 3 == 2
    int j0 = blockIdx.x * BLOCK_THREADS + threadIdx.x;
    int c0 = j0 % 3;   // base channel of float4 j (4 == 1 mod 3)
    for (int j = j0; j < n4; j += stride) {
        float4 v = in4[j];
        int c1 = c0 + 1; if (c1 == 3) c1 = 0;
        int c2 = c1 + 1; if (c2 == 3) c2 = 0;
        atomicAdd(&h[(c0 * NBINS + bin_of(v.x)) * NCOL], 1u);
        atomicAdd(&h[(c1 * NBINS + bin_of(v.y)) * NCOL], 1u);
        atomicAdd(&h[(c2 * NBINS + bin_of(v.z)) * NCOL], 1u);
        atomicAdd(&h[(c0 * NBINS + bin_of(v.w)) * NCOL], 1u);  // 4th wraps to c0
        c0--; if (c0 < 0) c0 = 2;   // advance by stride%3 == 2  ==  -1 (mod 3)
    }

    // Scalar tail (n_total % 4 != 0) — block 0 only (no-op for this shape)
    if (blockIdx.x == 0) {
        for (int i = n4 * 4 + threadIdx.x; i < n_total; i += BLOCK_THREADS) {
            int c = i % 3;
            atomicAdd(&h[(c * NBINS + bin_of(in[i])) * NCOL], 1u);
        }
    }

    __syncthreads();

    // Reduce the 16 columns per bin, publish block partial to L2 counters
    for (int i = threadIdx.x; i < NHIST; i += BLOCK_THREADS) {
        unsigned int s = 0u;
        #pragma unroll
        for (int c = 0; c < NCOL; c++) s += sh[i * NCOL + c];
        if (s) atomicAdd(&g_counts[i], s);
    }

    // Fused finalize: last block to arrive normalizes and resets state.
    __threadfence();
    __shared__ unsigned int ticket;
    if (threadIdx.x == 0) ticket = atomicAdd(&g_ticket, 1u);
    __syncthreads();
    if (ticket == GRID_BLOCKS - 1) {
        for (int i = threadIdx.x; i < NHIST; i += BLOCK_THREADS) {
            unsigned int s = atomicAdd(&g_counts[i], 0u);   // coherent read
            g_counts[i] = 0u;                               // reset for next call
            int c   = i >> 8;
            int bin = i & (NBINS - 1);
            // reference output is hist.T -> [nbins, 3] row-major
            out[bin * NCH + c] = (float)s * inv_total;
        }
        if (threadIdx.x == 0) g_ticket = 0u;                // reset ticket
    }
}

extern "C" void kernel_launch(void* const* d_in, const int* in_sizes, int n_in,
                              void* d_out, int out_size) {
    const float* in = (const float*)d_in[0];
    int n = in_sizes[0];                 // 64*512*512*3 = 50,331,648
    int n4 = n / 4;
    float inv_total = 1.0f / (float)(n / 3);   // per-channel pixel count (exact)

    hist_kernel<<<GRID_BLOCKS, BLOCK_THREADS>>>((const float4*)in, n4, in, n,
                                                (float*)d_out, inv_total);
}